// round 1
// baseline (speedup 1.0000x reference)
#include <cuda_runtime.h>
#include <math.h>

#define BB 64
#define NN 16384
#define CC 64
#define SLABS 8
#define NTOT (NN * CC)                 // 1,048,576 floats per sample
#define F4_PER_B (NTOT / 4)            // 262,144 float4 per sample
#define F4_PER_SLAB (F4_PER_B / SLABS) // 32,768 float4 per slab
#define F4_TOTAL ((long)BB * F4_PER_B) // 16,777,216

// __device__ scratch (no allocations allowed)
__device__ float g_psum[BB][SLABS][CC];
__device__ float g_psq [BB][SLABS][CC];
__device__ float g_scale[BB][CC];
__device__ float g_bias [BB][CC];

// ---------------------------------------------------------------------------
// Kernel 1: partial sums / sums-of-squares per (b, slab, c)
// grid = BB*SLABS blocks, 256 threads. Fully coalesced float4 stream.
// Because F4_PER_B, F4_PER_SLAB and blockDim are all multiples of 16,
// each thread's float4 always covers channels [(tid&15)*4 .. +3].
// ---------------------------------------------------------------------------
__global__ __launch_bounds__(256) void stats_partial_kernel(const float* __restrict__ x) {
    const int b    = blockIdx.x >> 3;
    const int slab = blockIdx.x & 7;
    const int tid  = threadIdx.x;
    const float4* __restrict__ x4 = reinterpret_cast<const float4*>(x);
    const long base = (long)b * F4_PER_B + (long)slab * F4_PER_SLAB;

    float4 s = make_float4(0.f, 0.f, 0.f, 0.f);
    float4 q = make_float4(0.f, 0.f, 0.f, 0.f);

    #pragma unroll 4
    for (int k = 0; k < F4_PER_SLAB / 256; k++) {
        float4 v = __ldg(&x4[base + (long)k * 256 + tid]);
        s.x += v.x; s.y += v.y; s.z += v.z; s.w += v.w;
        q.x = fmaf(v.x, v.x, q.x);
        q.y = fmaf(v.y, v.y, q.y);
        q.z = fmaf(v.z, v.z, q.z);
        q.w = fmaf(v.w, v.w, q.w);
    }

    __shared__ float4 ssum[256];
    __shared__ float4 ssq [256];
    ssum[tid] = s;
    ssq [tid] = q;
    __syncthreads();

    // 16 channel-quads; threads 0..15 each fold the 16 partials of quad tid
    if (tid < 16) {
        float4 S = make_float4(0.f, 0.f, 0.f, 0.f);
        float4 Q = make_float4(0.f, 0.f, 0.f, 0.f);
        #pragma unroll
        for (int m = 0; m < 16; m++) {
            float4 a = ssum[tid + 16 * m];
            float4 c = ssq [tid + 16 * m];
            S.x += a.x; S.y += a.y; S.z += a.z; S.w += a.w;
            Q.x += c.x; Q.y += c.y; Q.z += c.z; Q.w += c.w;
        }
        const int c0 = tid * 4;
        g_psum[b][slab][c0 + 0] = S.x;
        g_psum[b][slab][c0 + 1] = S.y;
        g_psum[b][slab][c0 + 2] = S.z;
        g_psum[b][slab][c0 + 3] = S.w;
        g_psq [b][slab][c0 + 0] = Q.x;
        g_psq [b][slab][c0 + 1] = Q.y;
        g_psq [b][slab][c0 + 2] = Q.z;
        g_psq [b][slab][c0 + 3] = Q.w;
    }
}

// ---------------------------------------------------------------------------
// Kernel 2: partner selection + per-(b,c) fused scale/bias.
// grid = BB blocks, CC threads. Each block recomputes its partner's stats
// from the partials (8 extra adds) -> no cross-block stat dependency.
// ---------------------------------------------------------------------------
__global__ __launch_bounds__(64) void finalize_kernel(const float* __restrict__ alpha_u,
                                                      const float* __restrict__ noise,
                                                      const int*   __restrict__ dom,
                                                      const int*   __restrict__ cls) {
    const int b = blockIdx.x;
    __shared__ int s_idx;

    if (threadIdx.x == 0) {
        const int cb = cls[b];
        const int db = dom[b];
        float best = -INFINITY;
        int bi = -1;
        #pragma unroll 1
        for (int j = 0; j < BB; j++) {
            if (cls[j] == cb && dom[j] != db) {
                float v = noise[b * BB + j];
                if (v > best) { best = v; bi = j; }  // strict > == first-max tie-break
            }
        }
        s_idx = (bi < 0) ? b : bi;
    }
    __syncthreads();
    const int idx = s_idx;
    const int c = threadIdx.x;

    float sum = 0.f, sq = 0.f, sum2 = 0.f, sq2 = 0.f;
    #pragma unroll
    for (int s = 0; s < SLABS; s++) {
        sum  += g_psum[b][s][c];
        sq   += g_psq [b][s][c];
        sum2 += g_psum[idx][s][c];
        sq2  += g_psq [idx][s][c];
    }

    const float inv_n   = 1.0f / 16384.0f;
    const float inv_nm1 = 1.0f / 16383.0f;
    const float eps = 1e-6f;

    float mu   = sum * inv_n;
    float var  = (sq  - sum  * sum  * inv_n) * inv_nm1;
    float sig  = sqrtf(var + eps);
    float mu2  = sum2 * inv_n;
    float var2 = (sq2 - sum2 * sum2 * inv_n) * inv_nm1;
    float sig2 = sqrtf(var2 + eps);

    float a = alpha_u[b] * 0.5f;   // ALPHA_MAX
    float mu_mix  = mu  * a + mu2  * (1.0f - a);
    float sig_mix = sig * a + sig2 * (1.0f - a);

    float sc = sig_mix / sig;
    g_scale[b][c] = sc;
    g_bias [b][c] = mu_mix - mu * sc;
}

// ---------------------------------------------------------------------------
// Kernel 3: out = x * scale[b][c] + bias[b][c], float4 grid-stride.
// ---------------------------------------------------------------------------
__global__ __launch_bounds__(256) void apply_kernel(const float* __restrict__ x,
                                                    float* __restrict__ out) {
    const float4* __restrict__ x4 = reinterpret_cast<const float4*>(x);
    float4* __restrict__ o4 = reinterpret_cast<float4*>(out);
    const float4* __restrict__ sc4 = reinterpret_cast<const float4*>(&g_scale[0][0]);
    const float4* __restrict__ bi4 = reinterpret_cast<const float4*>(&g_bias[0][0]);

    const long stride = (long)gridDim.x * blockDim.x;
    for (long i4 = (long)blockIdx.x * blockDim.x + threadIdx.x; i4 < F4_TOTAL; i4 += stride) {
        const int b  = (int)(i4 >> 18);          // / F4_PER_B (262144)
        const int cq = (int)(i4 & 15);           // channel-quad within row
        float4 v = __ldg(&x4[i4]);
        float4 s = __ldg(&sc4[b * 16 + cq]);
        float4 t = __ldg(&bi4[b * 16 + cq]);
        float4 r;
        r.x = fmaf(v.x, s.x, t.x);
        r.y = fmaf(v.y, s.y, t.y);
        r.z = fmaf(v.z, s.z, t.z);
        r.w = fmaf(v.w, s.w, t.w);
        o4[i4] = r;
    }
}

extern "C" void kernel_launch(void* const* d_in, const int* in_sizes, int n_in,
                              void* d_out, int out_size) {
    const float* x       = (const float*)d_in[0];
    const float* alpha_u = (const float*)d_in[1];
    const float* noise   = (const float*)d_in[2];
    const int*   dom     = (const int*)  d_in[3];
    const int*   cls     = (const int*)  d_in[4];
    float* out = (float*)d_out;

    stats_partial_kernel<<<BB * SLABS, 256>>>(x);
    finalize_kernel<<<BB, CC>>>(alpha_u, noise, dom, cls);
    // 4 float4 per thread: 16384 blocks * 256 thr * 4 = 16,777,216 = F4_TOTAL
    apply_kernel<<<16384, 256>>>(x, out);
}